// round 4
// baseline (speedup 1.0000x reference)
#include <cuda_runtime.h>
#include <math.h>

#define N_NODES 100000
#define N_EDGES 1600000
#define F_IN    128
#define HID     64
#define NCLS    40
#define SCAN_B  512
#define N_SCANB ((N_NODES + SCAN_B - 1) / SCAN_B)   // 196

// ---------------- scratch (no allocations allowed) ----------------
__device__ int   g_is64;
__device__ int   g_cnt [N_NODES];        // in-degree histogram (no self-loop)
__device__ int   g_off [N_NODES + 1];    // CSR row offsets (by dst)
__device__ int   g_cur [N_NODES];        // scatter cursors
__device__ int   g_bsum [256];
__device__ int   g_bsumx[256];
__device__ float g_dinv[N_NODES];
__device__ int   g_csr_src[N_EDGES];     // src per CSR slot (weights factored out)
__device__ __align__(16) float g_h1[N_NODES * HID];   // dinv * (x @ W1)  (pre-scaled)
__device__ __align__(16) float g_h2[N_NODES * NCLS];  // dinv * relu(a1+b1) @ W2

// ---------------- edge dtype sniffing ----------------
__global__ void k_detect(const int* __restrict__ ei32) {
    if (threadIdx.x == 0 && blockIdx.x == 0) {
        int nz = 0;
        for (int i = 0; i < 256; i++) nz += (ei32[2 * i + 1] != 0);
        g_is64 = (nz == 0) ? 1 : 0;
    }
}

__device__ __forceinline__ int edge_at(const void* ei, long long idx) {
    int v;
    if (g_is64) v = (int)((const long long*)ei)[idx];
    else        v = ((const int*)ei)[idx];
    return min(max(v, 0), N_NODES - 1);   // wrong guess -> rel_err, not fault
}

// ---------------- CSR build ----------------
__global__ void k_zero() {
    int i = blockIdx.x * blockDim.x + threadIdx.x;
    if (i < N_NODES) g_cnt[i] = 0;
}

__global__ void k_hist(const void* __restrict__ ei) {
    int e = blockIdx.x * blockDim.x + threadIdx.x;
    if (e < N_EDGES) atomicAdd(&g_cnt[edge_at(ei, (long long)N_EDGES + e)], 1);
}

__global__ void k_scan_block() {
    __shared__ int sh[SCAN_B];
    int i = blockIdx.x * SCAN_B + threadIdx.x;
    int v = (i < N_NODES) ? g_cnt[i] : 0;
    sh[threadIdx.x] = v;
    __syncthreads();
#pragma unroll
    for (int off = 1; off < SCAN_B; off <<= 1) {
        int t = (threadIdx.x >= off) ? sh[threadIdx.x - off] : 0;
        __syncthreads();
        sh[threadIdx.x] += t;
        __syncthreads();
    }
    if (i < N_NODES) g_off[i] = sh[threadIdx.x] - v;       // exclusive
    if (threadIdx.x == SCAN_B - 1) g_bsum[blockIdx.x] = sh[SCAN_B - 1];
}

__global__ void k_scan_top() {
    __shared__ int sh[256];
    int v = (threadIdx.x < N_SCANB) ? g_bsum[threadIdx.x] : 0;
    sh[threadIdx.x] = v;
    __syncthreads();
#pragma unroll
    for (int off = 1; off < 256; off <<= 1) {
        int t = (threadIdx.x >= off) ? sh[threadIdx.x - off] : 0;
        __syncthreads();
        sh[threadIdx.x] += t;
        __syncthreads();
    }
    g_bsumx[threadIdx.x] = sh[threadIdx.x] - v;            // exclusive
}

// finalize offsets + compute dinv + reset cursors (fused)
__global__ void k_scan_add() {
    int i = blockIdx.x * blockDim.x + threadIdx.x;
    if (i < N_NODES) {
        g_off[i] += g_bsumx[i >> 9];
        g_dinv[i] = rsqrtf((float)(g_cnt[i] + 1));   // +1 self-loop
        g_cur[i]  = 0;
    }
    if (i == 0) g_off[N_NODES] = N_EDGES;
}

__global__ void k_scatter(const void* __restrict__ ei) {
    int e = blockIdx.x * blockDim.x + threadIdx.x;
    if (e < N_EDGES) {
        int s = edge_at(ei, e);
        int d = edge_at(ei, (long long)N_EDGES + e);
        int pos = g_off[d] + atomicAdd(&g_cur[d], 1);
        g_csr_src[pos] = s;
    }
}

// -------- GEMM1: h1 = dinv * (x @ W1)   (100000x128 @ 128x64) ---------------
__global__ void k_gemm1(const float* __restrict__ x, const float* __restrict__ W) {
    __shared__ __align__(16) float Xs[128 * 64];  // 32KB
    __shared__ __align__(16) float Ws[64 * 64];   // 16KB
    const int t  = threadIdx.x;
    const int tx = t & 15;
    const int ty = t >> 4;
    const int row0 = blockIdx.x * 128;

    float acc[8][4];
#pragma unroll
    for (int r = 0; r < 8; r++)
#pragma unroll
        for (int c = 0; c < 4; c++) acc[r][c] = 0.0f;

    for (int kc = 0; kc < 2; kc++) {
#pragma unroll
        for (int j = 0; j < 8; j++) {
            int idx = t + j * 256;
            int r   = idx >> 4;
            int kq  = idx & 15;
            float4 v = make_float4(0.f, 0.f, 0.f, 0.f);
            if (row0 + r < N_NODES)
                v = *(const float4*)&x[(size_t)(row0 + r) * F_IN + kc * 64 + kq * 4];
            *(float4*)&Xs[r * 64 + kq * 4] = v;
        }
#pragma unroll
        for (int j = 0; j < 4; j++) {
            int idx = t + j * 256;
            int r   = idx >> 4;
            int kq  = idx & 15;
            *(float4*)&Ws[r * 64 + kq * 4] =
                *(const float4*)&W[(size_t)(kc * 64 + r) * HID + kq * 4];
        }
        __syncthreads();

#pragma unroll 4
        for (int k = 0; k < 64; k++) {
            float4 w = *(float4*)&Ws[k * 64 + tx * 4];
#pragma unroll
            for (int r = 0; r < 8; r++) {
                float xv = Xs[(ty + r * 16) * 64 + k];
                acc[r][0] = fmaf(xv, w.x, acc[r][0]);
                acc[r][1] = fmaf(xv, w.y, acc[r][1]);
                acc[r][2] = fmaf(xv, w.z, acc[r][2]);
                acc[r][3] = fmaf(xv, w.w, acc[r][3]);
            }
        }
        __syncthreads();
    }

#pragma unroll
    for (int r = 0; r < 8; r++) {
        int row = row0 + ty + r * 16;
        if (row < N_NODES) {
            float dv = g_dinv[row];
            *(float4*)&g_h1[(size_t)row * HID + tx * 4] =
                make_float4(acc[r][0] * dv, acc[r][1] * dv,
                            acc[r][2] * dv, acc[r][3] * dv);
        }
    }
}

// ---- fused: agg layer1 (CSR gather) + relu(a1+b1) @ W2 + prescale ----------
// warp per dst node; lane holds features 2*lane, 2*lane+1 of the 64-vector.
__global__ void k_agg1_gemm2(const float* __restrict__ b1, const float* __restrict__ W2) {
    __shared__ float Ws[HID * NCLS];  // 10KB, row-major [k][c]
    __shared__ float bs[HID];
    for (int i = threadIdx.x; i < HID * NCLS; i += 256) Ws[i] = W2[i];
    if (threadIdx.x < HID) bs[threadIdx.x] = b1[threadIdx.x];
    __syncthreads();

    unsigned gid = blockIdx.x * blockDim.x + threadIdx.x;
    int n    = gid >> 5;
    int lane = threadIdx.x & 31;
    if (n >= N_NODES) return;

    int beg = g_off[n], end = g_off[n + 1];
    float dv = g_dinv[n];

    // self-loop: a1[d] = dv * (sum_{s in N(d)} h1s[s] + h1s[d])
    float2 v = *(const float2*)&g_h1[(size_t)n * HID + lane * 2];
    float ax = v.x, ay = v.y;

    int e = beg;
    for (; e + 3 < end; e += 4) {
        int s0 = g_csr_src[e],     s1 = g_csr_src[e + 1];
        int s2 = g_csr_src[e + 2], s3 = g_csr_src[e + 3];
        float2 v0 = *(const float2*)&g_h1[(size_t)s0 * HID + lane * 2];
        float2 v1 = *(const float2*)&g_h1[(size_t)s1 * HID + lane * 2];
        float2 v2 = *(const float2*)&g_h1[(size_t)s2 * HID + lane * 2];
        float2 v3 = *(const float2*)&g_h1[(size_t)s3 * HID + lane * 2];
        ax += v0.x + v1.x + v2.x + v3.x;
        ay += v0.y + v1.y + v2.y + v3.y;
    }
    for (; e < end; e++) {
        int s = g_csr_src[e];
        float2 vv = *(const float2*)&g_h1[(size_t)s * HID + lane * 2];
        ax += vv.x; ay += vv.y;
    }

    // relu(a1 + b1) for this lane's two k-positions
    float act0 = fmaxf(fmaf(dv, ax, bs[2 * lane]),     0.0f);
    float act1 = fmaxf(fmaf(dv, ay, bs[2 * lane + 1]), 0.0f);

    // z[c] = sum_k act_k * W2[k][c]; lane c owns col c (and 32+c for c<8)
    float z0 = 0.0f, z1 = 0.0f;
#pragma unroll
    for (int kk = 0; kk < 32; kk++) {
        float va = __shfl_sync(0xffffffffu, act0, kk);
        float vb = __shfl_sync(0xffffffffu, act1, kk);
        z0 = fmaf(va, Ws[(2 * kk) * NCLS + lane], z0);
        z0 = fmaf(vb, Ws[(2 * kk + 1) * NCLS + lane], z0);
        if (lane < 8) {
            z1 = fmaf(va, Ws[(2 * kk) * NCLS + 32 + lane], z1);
            z1 = fmaf(vb, Ws[(2 * kk + 1) * NCLS + 32 + lane], z1);
        }
    }

    // store pre-scaled for next aggregation: h2s = dinv * h2
    g_h2[(size_t)n * NCLS + lane] = dv * z0;
    if (lane < 8) g_h2[(size_t)n * NCLS + 32 + lane] = dv * z1;
}

// ------- agg layer2 (CSR gather) + bias + log_softmax, warp per node --------
__global__ void k_agg2_softmax(float* __restrict__ out, const float* __restrict__ b2) {
    unsigned gid = blockIdx.x * blockDim.x + threadIdx.x;
    int n    = gid >> 5;
    int lane = threadIdx.x & 31;
    if (n >= N_NODES) return;

    int beg = g_off[n], end = g_off[n + 1];
    float dv = g_dinv[n];

    // self-loop contribution
    float a0 = g_h2[(size_t)n * NCLS + lane];
    float a1v = (lane < 8) ? g_h2[(size_t)n * NCLS + 32 + lane] : 0.0f;

    int e = beg;
    for (; e + 1 < end; e += 2) {
        int s0 = g_csr_src[e], s1 = g_csr_src[e + 1];
        a0 += g_h2[(size_t)s0 * NCLS + lane];
        a0 += g_h2[(size_t)s1 * NCLS + lane];
        if (lane < 8) {
            a1v += g_h2[(size_t)s0 * NCLS + 32 + lane];
            a1v += g_h2[(size_t)s1 * NCLS + 32 + lane];
        }
    }
    for (; e < end; e++) {
        int s = g_csr_src[e];
        a0 += g_h2[(size_t)s * NCLS + lane];
        if (lane < 8) a1v += g_h2[(size_t)s * NCLS + 32 + lane];
    }

    const float NEG_INF = __int_as_float(0xff800000);
    float z0 = fmaf(dv, a0, b2[lane]);
    float z1 = (lane < 8) ? fmaf(dv, a1v, b2[32 + lane]) : NEG_INF;

    float m = fmaxf(z0, z1);
#pragma unroll
    for (int off = 16; off > 0; off >>= 1)
        m = fmaxf(m, __shfl_xor_sync(0xffffffffu, m, off));

    float s = __expf(z0 - m) + ((lane < 8) ? __expf(z1 - m) : 0.0f);
#pragma unroll
    for (int off = 16; off > 0; off >>= 1)
        s += __shfl_xor_sync(0xffffffffu, s, off);

    float lse = m + __logf(s);
    out[(size_t)n * NCLS + lane] = z0 - lse;
    if (lane < 8) out[(size_t)n * NCLS + 32 + lane] = z1 - lse;
}

// ---------------- launch ----------------
extern "C" void kernel_launch(void* const* d_in, const int* in_sizes, int n_in,
                              void* d_out, int out_size) {
    const float* x  = nullptr;  const void* ei = nullptr;
    const float* W1 = nullptr;  const float* b1 = nullptr;
    const float* W2 = nullptr;  const float* b2 = nullptr;
    for (int i = 0; i < n_in; i++) {
        switch (in_sizes[i]) {
            case N_NODES * F_IN:  x  = (const float*)d_in[i]; break;
            case 2 * N_EDGES:     ei = d_in[i];               break;
            case F_IN * HID:      W1 = (const float*)d_in[i]; break;
            case HID:             b1 = (const float*)d_in[i]; break;
            case HID * NCLS:      W2 = (const float*)d_in[i]; break;
            case NCLS:            b2 = (const float*)d_in[i]; break;
            default: break;
        }
    }
    float* out = (float*)d_out;

    const int NB_N = (N_NODES + 255) / 256;
    const int NB_E = (N_EDGES + 255) / 256;
    const int NB_W = (N_NODES * 32 + 255) / 256;   // warp per node

    k_detect      <<<1, 32>>>((const int*)ei);
    k_zero        <<<NB_N, 256>>>();
    k_hist        <<<NB_E, 256>>>(ei);
    k_scan_block  <<<N_SCANB, SCAN_B>>>();
    k_scan_top    <<<1, 256>>>();
    k_scan_add    <<<NB_N, 256>>>();
    k_scatter     <<<NB_E, 256>>>(ei);

    k_gemm1       <<<(N_NODES + 127) / 128, 256>>>(x, W1);
    k_agg1_gemm2  <<<NB_W, 256>>>(b1, W2);
    k_agg2_softmax<<<NB_W, 256>>>(out, b2);
}